// round 7
// baseline (speedup 1.0000x reference)
#include <cuda_runtime.h>

#define Bn 4
#define Cn 256
#define ICn 128
#define Sn 64
#define NTOK (Bn*Sn)        // 256
#define REGION 1024
#define EPSf 1e-5f

#define PA_BLOCKS 256       // projattn grid (all co-resident: 8 warps/block)

// Scratch (allocation-free __device__ globals)
__device__ float d_P   [NTOK*Cn];      // pooled tokens [tok][c]
__device__ float d_g   [NTOK*ICn];
__device__ float d_th  [NTOK*ICn];
__device__ float d_ph  [NTOK*ICn];
__device__ float d_Wt  [ICn*Cn];       // BN-folded W transposed: [i][c]
__device__ float d_bias[Cn];           // BN-folded bias
__device__ float d_val [Bn*Cn*Sn];     // broadcast values [b][c][s]

// grid barrier (generation counter persists across graph replays)
__device__ unsigned g_cnt = 0;
__device__ unsigned g_gen = 0;

// ---------------------------------------------------------------------------
// K1: stripe mean pool (blocks 0..8191) + BN-fold of W (blocks 8192..8199).
// ---------------------------------------------------------------------------
__global__ void pool_kernel(const float* __restrict__ x,
                            const float* __restrict__ W_w,  const float* __restrict__ W_b,
                            const float* __restrict__ gamma,const float* __restrict__ beta,
                            const float* __restrict__ mean, const float* __restrict__ var) {
    int tid = threadIdx.x;
    if (blockIdx.x >= 8192) {
        // BN fold + transpose of W: 8 blocks x 256 threads x 16 elems
        int base = (blockIdx.x - 8192) * 4096;
#pragma unroll
        for (int l = 0; l < 16; l++) {
            int idx = base + l * 256 + tid;        // over [c][i]
            int c = idx >> 7, i = idx & 127;
            float inv = gamma[c] * rsqrtf(var[c] + EPSf);
            d_Wt[i * Cn + c] = W_w[idx] * inv;
        }
        if (blockIdx.x == 8192) {
            int c = tid;
            float inv = gamma[c] * rsqrtf(var[c] + EPSf);
            d_bias[c] = (W_b[c] - mean[c]) * inv + beta[c];
        }
        return;
    }
    int warp = (blockIdx.x * blockDim.x + tid) >> 5;   // 0..65535
    int lane = tid & 31;
    const float4* p = (const float4*)(x + (size_t)warp * REGION);
    float sum = 0.f;
#pragma unroll
    for (int i = 0; i < 8; i++) {
        float4 v = p[lane + i * 32];
        sum += (v.x + v.y) + (v.z + v.w);
    }
#pragma unroll
    for (int o = 16; o; o >>= 1) sum += __shfl_down_sync(0xffffffffu, sum, o);
    if (lane == 0) {
        int b   = warp >> 14;
        int rem = warp & 16383;
        int c   = rem >> 6;
        int s   = rem & 63;
        d_P[(b * Sn + s) * Cn + c] = sum * (1.0f / REGION);
    }
}

// ---------------------------------------------------------------------------
// K2: fused projections + attention + output projection.
// Phase 1 (blocks 0..95): g/th/ph tiled GEMM (32x32 tiles).
// grid barrier.
// Phase 2 (all 256 blocks): per-token attention row + Wt epilogue -> d_val.
// ---------------------------------------------------------------------------
__global__ void __launch_bounds__(256, 8) projattn_kernel(
        const float* __restrict__ g_w,  const float* __restrict__ g_b,
        const float* __restrict__ th_w, const float* __restrict__ th_b,
        const float* __restrict__ ph_w, const float* __restrict__ ph_b) {
    __shared__ float As[32][33];
    __shared__ float Bs[32][33];
    __shared__ float at_s[Sn];
    __shared__ float y_s[ICn];

    int tid = threadIdx.x;
    int blk = blockIdx.x;

    // ---------------- Phase 1: projections ----------------
    if (blk < 96) {
        int t0 = (blk & 7) * 32;
        int oT = blk >> 3;                   // 0..11
        int mat  = oT >> 2;
        int row0 = (oT & 3) * 32;
        const float* wsrc = (mat == 0) ? g_w : (mat == 1) ? th_w : ph_w;
        const float* bsrc = (mat == 0) ? g_b : (mat == 1) ? th_b : ph_b;
        float*       osrc = (mat == 0) ? d_g : (mat == 1) ? d_th : d_ph;

        int tx = tid & 15, ty = tid >> 4;
        float acc[2][2] = {{0.f,0.f},{0.f,0.f}};

        for (int k0 = 0; k0 < Cn; k0 += 32) {
#pragma unroll
            for (int l = 0; l < 4; l++) {
                int idx = tid + l * 256;
                int r = idx >> 5, k = idx & 31;
                As[r][k] = d_P[(t0 + r) * Cn + k0 + k];
                Bs[r][k] = wsrc[(row0 + r) * Cn + k0 + k];
            }
            __syncthreads();
#pragma unroll
            for (int k = 0; k < 32; k++) {
                float a0 = As[ty * 2][k], a1 = As[ty * 2 + 1][k];
                float b0 = Bs[tx * 2][k], b1 = Bs[tx * 2 + 1][k];
                acc[0][0] = fmaf(a0, b0, acc[0][0]);
                acc[0][1] = fmaf(a0, b1, acc[0][1]);
                acc[1][0] = fmaf(a1, b0, acc[1][0]);
                acc[1][1] = fmaf(a1, b1, acc[1][1]);
            }
            __syncthreads();
        }
#pragma unroll
        for (int di = 0; di < 2; di++)
#pragma unroll
            for (int dj = 0; dj < 2; dj++) {
                int tok = t0 + ty * 2 + di;
                int i   = row0 + tx * 2 + dj;
                osrc[tok * ICn + i] = acc[di][dj] + bsrc[i];
            }
    }

    // ---------------- grid barrier ----------------
    __syncthreads();
    if (tid == 0) {
        unsigned gen = *(volatile unsigned*)&g_gen;
        __threadfence();
        if (atomicAdd(&g_cnt, 1) == PA_BLOCKS - 1) {
            g_cnt = 0;
            __threadfence();
            *(volatile unsigned*)&g_gen = gen + 1;
        } else {
            while (*(volatile unsigned*)&g_gen == gen) { }
        }
        __threadfence();
    }
    __syncthreads();

    // ---------------- Phase 2: attention row + epilogue ----------------
    int bs = blk;                        // b*Sn + s
    int b  = bs >> 6;
    int s  = bs & 63;
    int warp = tid >> 5, lane = tid & 31;

    // theta row into As storage (reuse as flat float buffer)
    float* th_s = &As[0][0];
    if (tid < ICn) th_s[tid] = d_th[bs * ICn + tid];
    __syncthreads();

    const float4* th4 = (const float4*)th_s;
    float4 a = th4[lane];
#pragma unroll
    for (int d = 0; d < 8; d++) {
        int r = warp * 8 + d;
        float4 p = ((const float4*)(d_ph + (b * Sn + r) * ICn))[lane];
        float acc = a.x * p.x + a.y * p.y + a.z * p.z + a.w * p.w;
#pragma unroll
        for (int o = 16; o; o >>= 1) acc += __shfl_down_sync(0xffffffffu, acc, o);
        if (lane == 0) at_s[r] = acc;
    }
    __syncthreads();

    if (warp == 0) {
        float v0 = at_s[lane], v1 = at_s[lane + 32];
        float m = fmaxf(v0, v1);
#pragma unroll
        for (int o = 16; o; o >>= 1) m = fmaxf(m, __shfl_xor_sync(0xffffffffu, m, o));
        float e0 = __expf(v0 - m), e1 = __expf(v1 - m);
        float sum = e0 + e1;
#pragma unroll
        for (int o = 16; o; o >>= 1) sum += __shfl_xor_sync(0xffffffffu, sum, o);
        float inv = 1.0f / sum;
        at_s[lane]      = e0 * inv;
        at_s[lane + 32] = e1 * inv;
    }
    __syncthreads();

    if (tid < ICn) {
        const float* gb = d_g + b * Sn * ICn + tid;
        float acc = 0.f;
#pragma unroll 16
        for (int r = 0; r < Sn; r++) acc = fmaf(at_s[r], gb[r * ICn], acc);
        y_s[tid] = acc;
    }
    __syncthreads();

    {
        const float* wt = d_Wt + tid;    // stride Cn per i, coalesced over c
        float acc = 0.f;
#pragma unroll 8
        for (int i = 0; i < ICn; i++)
            acc = fmaf(y_s[i], wt[i * Cn], acc);
        d_val[(b * Cn + tid) * Sn + s] = acc + d_bias[tid];
    }
}

// ---------------------------------------------------------------------------
// K3: broadcast + residual. 8 float4 per thread, strided (keeps coalescing).
// ---------------------------------------------------------------------------
__global__ void residual_kernel(const float* __restrict__ x, float* __restrict__ z) {
    const int STRIDE = 8192 * 256;                    // threads in grid
    int t = blockIdx.x * 256 + threadIdx.x;
#pragma unroll
    for (int k = 0; k < 8; k++) {
        int idx = t + k * STRIDE;
        float v = d_val[idx >> 8];
        float4 a = ((const float4*)x)[idx];
        a.x += v; a.y += v; a.z += v; a.w += v;
        ((float4*)z)[idx] = a;
    }
}

// ---------------------------------------------------------------------------
extern "C" void kernel_launch(void* const* d_in, const int* in_sizes, int n_in,
                              void* d_out, int out_size) {
    const float* x      = (const float*)d_in[0];
    const float* g_w    = (const float*)d_in[1];
    const float* g_b    = (const float*)d_in[2];
    const float* th_w   = (const float*)d_in[3];
    const float* th_b   = (const float*)d_in[4];
    const float* ph_w   = (const float*)d_in[5];
    const float* ph_b   = (const float*)d_in[6];
    const float* W_w    = (const float*)d_in[7];
    const float* W_b    = (const float*)d_in[8];
    const float* gamma  = (const float*)d_in[9];
    const float* beta   = (const float*)d_in[10];
    const float* mean   = (const float*)d_in[11];
    const float* var    = (const float*)d_in[12];
    float* z = (float*)d_out;

    pool_kernel<<<8192 + 8, 256>>>(x, W_w, W_b, gamma, beta, mean, var);
    projattn_kernel<<<PA_BLOCKS, 256>>>(g_w, g_b, th_w, th_b, ph_w, ph_b);
    residual_kernel<<<8192, 256>>>(x, z);
}